// round 1
// baseline (speedup 1.0000x reference)
#include <cuda_runtime.h>
#include <cuda_bf16.h>
#include <cstdint>

#define N_NODES 100000
#define N_EDGES 1600000
#define D 128

// Scratch (allocation-free: __device__ globals)
__device__ float g_deg[N_NODES];            // becomes inv_deg in place
__device__ float g_agg[(size_t)N_NODES * D];
__device__ float g_h1[(size_t)N_NODES * D];
__device__ float g_h2[(size_t)N_NODES * D];

// ---------------------------------------------------------------- helpers
__device__ __forceinline__ unsigned long long pack_dup(float x) {
    unsigned long long r;
    asm("mov.b64 %0, {%1, %1};" : "=l"(r) : "f"(x));
    return r;
}
__device__ __forceinline__ void fma2(unsigned long long& acc, unsigned long long a,
                                     unsigned long long b) {
    asm("fma.rn.f32x2 %0, %1, %2, %0;" : "+l"(acc) : "l"(a), "l"(b));
}
__device__ __forceinline__ float2 unpack2(unsigned long long v) {
    float2 r;
    asm("mov.b64 {%0, %1}, %2;" : "=f"(r.x), "=f"(r.y) : "l"(v));
    return r;
}

// ---------------------------------------------------------------- kernels
__global__ void zero4_kernel(float4* __restrict__ p, int n4) {
    int i = blockIdx.x * blockDim.x + threadIdx.x;
    int st = gridDim.x * blockDim.x;
    for (; i < n4; i += st) p[i] = make_float4(0.f, 0.f, 0.f, 0.f);
}

__global__ void deg_kernel(const int* __restrict__ dst, float* __restrict__ deg, int E) {
    int i = blockIdx.x * blockDim.x + threadIdx.x;
    if (i < E) atomicAdd(&deg[dst[i]], 1.0f);
}

__global__ void invdeg_kernel(float* __restrict__ deg, int n) {
    int i = blockIdx.x * blockDim.x + threadIdx.x;
    if (i < n) deg[i] = 1.0f / fmaxf(deg[i], 1.0f);
}

// warp per edge: gather 512B row from H[src], vector-reduce into agg[dst]
__global__ void scatter_kernel(const float* __restrict__ H, const int* __restrict__ src,
                               const int* __restrict__ dst, float* __restrict__ agg, int E) {
    int nwarps = (gridDim.x * blockDim.x) >> 5;
    int w = (blockIdx.x * blockDim.x + threadIdx.x) >> 5;
    int lane = threadIdx.x & 31;
    for (int e = w; e < E; e += nwarps) {
        int s = __ldg(src + e);
        int d = __ldg(dst + e);
        float4 v = __ldg((const float4*)(H + (size_t)s * D) + lane);
        float* p = agg + (size_t)d * D + lane * 4;
        asm volatile("red.global.add.v4.f32 [%0], {%1, %2, %3, %4};"
                     :: "l"(p), "f"(v.x), "f"(v.y), "f"(v.z), "f"(v.w) : "memory");
    }
}

// out[M,128] = relu?( X @ Wself + (AGG * invdeg) @ Wneigh + bias )
// Tile: 128 rows x 128 cols, 256 threads, BK=16, f32x2 packed FMA.
#define BK 16
__global__ void __launch_bounds__(256, 2)
gemm_sage(const float* __restrict__ X, const float* __restrict__ AGG,
          const float* __restrict__ invdeg, const float* __restrict__ Wself,
          const float* __restrict__ Wneigh, const float* __restrict__ bias,
          float* __restrict__ out, int M, int doRelu) {
    __shared__ float As[BK][128];   // transposed: As[k][m]
    __shared__ float Bs[BK][128];   // Bs[k][n]

    int tid = threadIdx.x;
    int row0 = blockIdx.x * 128;
    int tx = tid & 15;   // n-group
    int ty = tid >> 4;   // m-group

    // A-load mapping: 128 rows x 16 k / 256 thr = 8 floats each
    int lrow = tid & 127;
    int lquad = tid >> 7;               // 0..1 -> k offset 8*lquad
    int arow = min(row0 + lrow, M - 1); // clamp (stores guarded)
    // B-load mapping: 16 k-rows x 128 n / 256 thr = 8 floats each
    int bkr = tid >> 4;                 // 0..15
    int bn = (tid & 15) * 8;

    // acc[i2][j]: m-pair i2 (rows ty*8+2*i2, +1), n index j (cols tx*4+j and 64+tx*4+j-4)
    unsigned long long acc[4][8];
#pragma unroll
    for (int i = 0; i < 4; i++)
#pragma unroll
        for (int j = 0; j < 8; j++) acc[i][j] = 0ULL;

#pragma unroll 1
    for (int phase = 0; phase < 2; ++phase) {
        const float* A = phase ? AGG : X;
        const float* W = phase ? Wneigh : Wself;
        float ascale = phase ? __ldg(invdeg + arow) : 1.0f;
        const float* Arow = A + (size_t)arow * D;

#pragma unroll 1
        for (int k0 = 0; k0 < D; k0 += BK) {
            __syncthreads();
            // load A chunk -> transposed smem, with scale
            {
                const float* ag = Arow + k0 + lquad * 8;
                float4 a0 = __ldg((const float4*)ag);
                float4 a1 = __ldg((const float4*)(ag + 4));
                a0.x *= ascale; a0.y *= ascale; a0.z *= ascale; a0.w *= ascale;
                a1.x *= ascale; a1.y *= ascale; a1.z *= ascale; a1.w *= ascale;
                int kb = lquad * 8;
                As[kb + 0][lrow] = a0.x; As[kb + 1][lrow] = a0.y;
                As[kb + 2][lrow] = a0.z; As[kb + 3][lrow] = a0.w;
                As[kb + 4][lrow] = a1.x; As[kb + 5][lrow] = a1.y;
                As[kb + 6][lrow] = a1.z; As[kb + 7][lrow] = a1.w;
            }
            // load W chunk
            {
                const float* wg = W + (size_t)(k0 + bkr) * D + bn;
                float4 w0 = __ldg((const float4*)wg);
                float4 w1 = __ldg((const float4*)(wg + 4));
                *(float4*)&Bs[bkr][bn] = w0;
                *(float4*)&Bs[bkr][bn + 4] = w1;
            }
            __syncthreads();

#pragma unroll
            for (int k = 0; k < BK; ++k) {
                const unsigned long long* ap =
                    (const unsigned long long*)&As[k][ty * 8];
                unsigned long long a2[4] = {ap[0], ap[1], ap[2], ap[3]};
                float4 B0 = *(const float4*)&Bs[k][tx * 4];
                float4 B1 = *(const float4*)&Bs[k][64 + tx * 4];
                unsigned long long b2[8];
                b2[0] = pack_dup(B0.x); b2[1] = pack_dup(B0.y);
                b2[2] = pack_dup(B0.z); b2[3] = pack_dup(B0.w);
                b2[4] = pack_dup(B1.x); b2[5] = pack_dup(B1.y);
                b2[6] = pack_dup(B1.z); b2[7] = pack_dup(B1.w);
#pragma unroll
                for (int i = 0; i < 4; i++)
#pragma unroll
                    for (int j = 0; j < 8; j++) fma2(acc[i][j], a2[i], b2[j]);
            }
        }
    }

    // epilogue
    float4 bias0 = __ldg((const float4*)(bias + tx * 4));
    float4 bias1 = __ldg((const float4*)(bias + 64 + tx * 4));
    const float bA[4] = {bias0.x, bias0.y, bias0.z, bias0.w};
    const float bB[4] = {bias1.x, bias1.y, bias1.z, bias1.w};

#pragma unroll
    for (int i2 = 0; i2 < 4; i2++) {
        int m0 = row0 + ty * 8 + i2 * 2;
        int m1 = m0 + 1;
        float loA[4], hiA[4], loB[4], hiB[4];
#pragma unroll
        for (int j = 0; j < 4; j++) {
            float2 v = unpack2(acc[i2][j]);
            loA[j] = v.x + bA[j]; hiA[j] = v.y + bA[j];
            float2 w = unpack2(acc[i2][j + 4]);
            loB[j] = w.x + bB[j]; hiB[j] = w.y + bB[j];
        }
        if (doRelu) {
#pragma unroll
            for (int j = 0; j < 4; j++) {
                loA[j] = fmaxf(loA[j], 0.f); hiA[j] = fmaxf(hiA[j], 0.f);
                loB[j] = fmaxf(loB[j], 0.f); hiB[j] = fmaxf(hiB[j], 0.f);
            }
        }
        if (m0 < M) {
            *(float4*)&out[(size_t)m0 * D + tx * 4] =
                make_float4(loA[0], loA[1], loA[2], loA[3]);
            *(float4*)&out[(size_t)m0 * D + 64 + tx * 4] =
                make_float4(loB[0], loB[1], loB[2], loB[3]);
        }
        if (m1 < M) {
            *(float4*)&out[(size_t)m1 * D + tx * 4] =
                make_float4(hiA[0], hiA[1], hiA[2], hiA[3]);
            *(float4*)&out[(size_t)m1 * D + 64 + tx * 4] =
                make_float4(hiB[0], hiB[1], hiB[2], hiB[3]);
        }
    }
}

// out[m, 0:2] = h2[m,:] @ Wc + bc ; warp per node
__global__ void cls_kernel(const float* __restrict__ H, const float* __restrict__ Wc,
                           const float* __restrict__ bc, float* __restrict__ out, int M) {
    int nwarps = (gridDim.x * blockDim.x) >> 5;
    int w = (blockIdx.x * blockDim.x + threadIdx.x) >> 5;
    int lane = threadIdx.x & 31;
    float b0 = __ldg(bc), b1 = __ldg(bc + 1);
    // Wc rows k = lane*4 .. lane*4+3, 2 floats each
    float4 w0 = __ldg((const float4*)Wc + lane * 2);
    float4 w1 = __ldg((const float4*)Wc + lane * 2 + 1);
    for (int m = w; m < M; m += nwarps) {
        float4 h = __ldg((const float4*)(H + (size_t)m * D) + lane);
        float a0 = h.x * w0.x + h.y * w0.z + h.z * w1.x + h.w * w1.z;
        float a1 = h.x * w0.y + h.y * w0.w + h.z * w1.y + h.w * w1.w;
#pragma unroll
        for (int off = 16; off; off >>= 1) {
            a0 += __shfl_xor_sync(0xFFFFFFFFu, a0, off);
            a1 += __shfl_xor_sync(0xFFFFFFFFu, a1, off);
        }
        if (lane == 0) {
            out[(size_t)m * 2 + 0] = a0 + b0;
            out[(size_t)m * 2 + 1] = a1 + b1;
        }
    }
}

// ---------------------------------------------------------------- launch
extern "C" void kernel_launch(void* const* d_in, const int* in_sizes, int n_in,
                              void* d_out, int out_size) {
    const float* features = (const float*)d_in[0];
    const int*   src      = (const int*)d_in[1];
    const int*   dst      = (const int*)d_in[2];
    const float* W1s      = (const float*)d_in[3];
    const float* W1n      = (const float*)d_in[4];
    const float* b1       = (const float*)d_in[5];
    const float* W2s      = (const float*)d_in[6];
    const float* W2n      = (const float*)d_in[7];
    const float* b2       = (const float*)d_in[8];
    const float* Wc       = (const float*)d_in[9];
    const float* bc       = (const float*)d_in[10];

    int N = in_sizes[0] / D;
    int E = in_sizes[1];

    float *agg, *deg, *h1, *h2;
    cudaGetSymbolAddress((void**)&agg, g_agg);
    cudaGetSymbolAddress((void**)&deg, g_deg);
    cudaGetSymbolAddress((void**)&h1, g_h1);
    cudaGetSymbolAddress((void**)&h2, g_h2);

    int mblocks = (N + 127) / 128;

    zero4_kernel<<<2048, 256>>>((float4*)agg, N * (D / 4));
    zero4_kernel<<<64, 256>>>((float4*)deg, N / 4);
    deg_kernel<<<(E + 255) / 256, 256>>>(dst, deg, E);
    invdeg_kernel<<<(N + 255) / 256, 256>>>(deg, N);

    scatter_kernel<<<4096, 256>>>(features, src, dst, agg, E);
    gemm_sage<<<mblocks, 256>>>(features, agg, deg, W1s, W1n, b1, h1, N, 1);

    zero4_kernel<<<2048, 256>>>((float4*)agg, N * (D / 4));
    scatter_kernel<<<4096, 256>>>(h1, src, dst, agg, E);
    gemm_sage<<<mblocks, 256>>>(h1, agg, deg, W2s, W2n, b2, h2, N, 0);

    cls_kernel<<<2048, 256>>>(h2, Wc, bc, (float*)d_out, N);
}

// round 2
// speedup vs baseline: 1.1137x; 1.1137x over previous
#include <cuda_runtime.h>
#include <cuda_bf16.h>
#include <cstdint>

#define N_NODES 100000
#define N_EDGES 1600000
#define D 128

// Scratch (allocation-free: __device__ globals)
__device__ int   g_cnt[N_NODES];
__device__ int   g_cursor[N_NODES];
__device__ int   g_rowstart[N_NODES + 1];
__device__ int   g_csrsrc[N_EDGES];
__device__ float g_agg[(size_t)N_NODES * D];
__device__ float g_h1[(size_t)N_NODES * D];

// ---------------------------------------------------------------- helpers
__device__ __forceinline__ unsigned long long pack_dup(float x) {
    unsigned long long r;
    asm("mov.b64 %0, {%1, %1};" : "=l"(r) : "f"(x));
    return r;
}
__device__ __forceinline__ void fma2(unsigned long long& acc, unsigned long long a,
                                     unsigned long long b) {
    asm("fma.rn.f32x2 %0, %1, %2, %0;" : "+l"(acc) : "l"(a), "l"(b));
}
__device__ __forceinline__ float2 unpack2(unsigned long long v) {
    float2 r;
    asm("mov.b64 {%0, %1}, %2;" : "=f"(r.x), "=f"(r.y) : "l"(v));
    return r;
}

// ---------------------------------------------------------------- CSR build
__global__ void hist_kernel(const int* __restrict__ dst, int* __restrict__ cnt, int E) {
    int i = blockIdx.x * blockDim.x + threadIdx.x;
    if (i < E) atomicAdd(&cnt[dst[i]], 1);
}

// single-block exclusive scan over cnt -> rowstart & cursor
__global__ void scan_kernel(const int* __restrict__ cnt, int* __restrict__ rowstart,
                            int* __restrict__ cursor, int n) {
    __shared__ int sums[1024];
    int tid = threadIdx.x;
    int per = (n + 1023) / 1024;
    int beg = tid * per;
    int end = min(beg + per, n);
    int s = 0;
    for (int i = beg; i < end; i++) s += cnt[i];
    sums[tid] = s;
    __syncthreads();
#pragma unroll
    for (int off = 1; off < 1024; off <<= 1) {
        int t = (tid >= off) ? sums[tid - off] : 0;
        __syncthreads();
        sums[tid] += t;
        __syncthreads();
    }
    int run = sums[tid] - s;  // exclusive prefix
    for (int i = beg; i < end; i++) {
        rowstart[i] = run;
        cursor[i] = run;
        run += cnt[i];
    }
    if (tid == 1023) rowstart[n] = sums[1023];
}

__global__ void fill_kernel(const int* __restrict__ src, const int* __restrict__ dst,
                            int* __restrict__ cursor, int* __restrict__ csrsrc, int E) {
    int i = blockIdx.x * blockDim.x + threadIdx.x;
    if (i < E) {
        int pos = atomicAdd(&cursor[dst[i]], 1);
        csrsrc[pos] = src[i];
    }
}

// ---------------------------------------------------------------- aggregation
// warp per dst node: gather + mean, no atomics, inv-deg fused
__global__ void gather_kernel(const float* __restrict__ H, const int* __restrict__ rowstart,
                              const int* __restrict__ csrsrc, float* __restrict__ agg, int N) {
    int w = (blockIdx.x * blockDim.x + threadIdx.x) >> 5;
    int lane = threadIdx.x & 31;
    if (w >= N) return;
    int beg = __ldg(rowstart + w);
    int end = __ldg(rowstart + w + 1);
    float4 a0 = make_float4(0.f, 0.f, 0.f, 0.f);
    float4 a1 = make_float4(0.f, 0.f, 0.f, 0.f);
    int i = beg;
    for (; i + 1 < end; i += 2) {
        int s0 = __ldg(csrsrc + i);
        int s1 = __ldg(csrsrc + i + 1);
        float4 v0 = __ldg((const float4*)(H + (size_t)s0 * D) + lane);
        float4 v1 = __ldg((const float4*)(H + (size_t)s1 * D) + lane);
        a0.x += v0.x; a0.y += v0.y; a0.z += v0.z; a0.w += v0.w;
        a1.x += v1.x; a1.y += v1.y; a1.z += v1.z; a1.w += v1.w;
    }
    if (i < end) {
        int s0 = __ldg(csrsrc + i);
        float4 v0 = __ldg((const float4*)(H + (size_t)s0 * D) + lane);
        a0.x += v0.x; a0.y += v0.y; a0.z += v0.z; a0.w += v0.w;
    }
    float inv = 1.0f / (float)max(end - beg, 1);
    float4 r = make_float4((a0.x + a1.x) * inv, (a0.y + a1.y) * inv,
                           (a0.z + a1.z) * inv, (a0.w + a1.w) * inv);
    *((float4*)(agg + (size_t)w * D) + lane) = r;
}

// ---------------------------------------------------------------- GEMM
// out[M,128] = relu?( X @ Wself + AGG @ Wneigh + bias )
// mode 0: relu, write features to out
// mode 1: no relu, fused classifier: out2[m,0:2] = h @ Wc + bc
#define BK 16
__global__ void __launch_bounds__(256, 2)
gemm_sage(const float* __restrict__ X, const float* __restrict__ AGG,
          const float* __restrict__ Wself, const float* __restrict__ Wneigh,
          const float* __restrict__ bias, float* __restrict__ out, int M, int mode,
          const float* __restrict__ Wc, const float* __restrict__ bc,
          float* __restrict__ out2) {
    __shared__ float As[BK][128];   // transposed: As[k][m]
    __shared__ float Bs[BK][128];   // Bs[k][n]

    int tid = threadIdx.x;
    int row0 = blockIdx.x * 128;
    int tx = tid & 15;   // n-group
    int ty = tid >> 4;   // m-group

    int lrow = tid & 127;
    int lquad = tid >> 7;               // 0..1 -> k offset 8*lquad
    int arow = min(row0 + lrow, M - 1); // clamp (stores guarded)
    int bkr = tid >> 4;                 // 0..15
    int bn = (tid & 15) * 8;

    unsigned long long acc[4][8];
#pragma unroll
    for (int i = 0; i < 4; i++)
#pragma unroll
        for (int j = 0; j < 8; j++) acc[i][j] = 0ULL;

#pragma unroll 1
    for (int phase = 0; phase < 2; ++phase) {
        const float* A = phase ? AGG : X;
        const float* W = phase ? Wneigh : Wself;
        const float* Arow = A + (size_t)arow * D;

#pragma unroll 1
        for (int k0 = 0; k0 < D; k0 += BK) {
            __syncthreads();
            {
                const float* ag = Arow + k0 + lquad * 8;
                float4 a0 = __ldg((const float4*)ag);
                float4 a1 = __ldg((const float4*)(ag + 4));
                int kb = lquad * 8;
                As[kb + 0][lrow] = a0.x; As[kb + 1][lrow] = a0.y;
                As[kb + 2][lrow] = a0.z; As[kb + 3][lrow] = a0.w;
                As[kb + 4][lrow] = a1.x; As[kb + 5][lrow] = a1.y;
                As[kb + 6][lrow] = a1.z; As[kb + 7][lrow] = a1.w;
            }
            {
                const float* wg = W + (size_t)(k0 + bkr) * D + bn;
                float4 w0 = __ldg((const float4*)wg);
                float4 w1 = __ldg((const float4*)(wg + 4));
                *(float4*)&Bs[bkr][bn] = w0;
                *(float4*)&Bs[bkr][bn + 4] = w1;
            }
            __syncthreads();

#pragma unroll
            for (int k = 0; k < BK; ++k) {
                const unsigned long long* ap =
                    (const unsigned long long*)&As[k][ty * 8];
                unsigned long long a2[4] = {ap[0], ap[1], ap[2], ap[3]};
                float4 B0 = *(const float4*)&Bs[k][tx * 4];
                float4 B1 = *(const float4*)&Bs[k][64 + tx * 4];
                unsigned long long b2[8];
                b2[0] = pack_dup(B0.x); b2[1] = pack_dup(B0.y);
                b2[2] = pack_dup(B0.z); b2[3] = pack_dup(B0.w);
                b2[4] = pack_dup(B1.x); b2[5] = pack_dup(B1.y);
                b2[6] = pack_dup(B1.z); b2[7] = pack_dup(B1.w);
#pragma unroll
                for (int i = 0; i < 4; i++)
#pragma unroll
                    for (int j = 0; j < 8; j++) fma2(acc[i][j], a2[i], b2[j]);
            }
        }
    }

    // epilogue
    float4 bias0 = __ldg((const float4*)(bias + tx * 4));
    float4 bias1 = __ldg((const float4*)(bias + 64 + tx * 4));
    const float bA[4] = {bias0.x, bias0.y, bias0.z, bias0.w};
    const float bB[4] = {bias1.x, bias1.y, bias1.z, bias1.w};

    if (mode == 0) {
#pragma unroll
        for (int i2 = 0; i2 < 4; i2++) {
            int m0 = row0 + ty * 8 + i2 * 2;
            int m1 = m0 + 1;
            float loA[4], hiA[4], loB[4], hiB[4];
#pragma unroll
            for (int j = 0; j < 4; j++) {
                float2 v = unpack2(acc[i2][j]);
                loA[j] = fmaxf(v.x + bA[j], 0.f);
                hiA[j] = fmaxf(v.y + bA[j], 0.f);
                float2 w = unpack2(acc[i2][j + 4]);
                loB[j] = fmaxf(w.x + bB[j], 0.f);
                hiB[j] = fmaxf(w.y + bB[j], 0.f);
            }
            if (m0 < M) {
                *(float4*)&out[(size_t)m0 * D + tx * 4] =
                    make_float4(loA[0], loA[1], loA[2], loA[3]);
                *(float4*)&out[(size_t)m0 * D + 64 + tx * 4] =
                    make_float4(loB[0], loB[1], loB[2], loB[3]);
            }
            if (m1 < M) {
                *(float4*)&out[(size_t)m1 * D + tx * 4] =
                    make_float4(hiA[0], hiA[1], hiA[2], hiA[3]);
                *(float4*)&out[(size_t)m1 * D + 64 + tx * 4] =
                    make_float4(hiB[0], hiB[1], hiB[2], hiB[3]);
            }
        }
    } else {
        // fused classifier: per-thread partial dot over its 8 columns,
        // reduce over the 16 tx threads (low 4 lane bits), write [m,2]
        float wc0[8], wc1[8];
#pragma unroll
        for (int j = 0; j < 4; j++) {
            int c0 = tx * 4 + j;
            int c1 = 64 + tx * 4 + j;
            wc0[j]     = __ldg(Wc + c0 * 2);
            wc1[j]     = __ldg(Wc + c0 * 2 + 1);
            wc0[j + 4] = __ldg(Wc + c1 * 2);
            wc1[j + 4] = __ldg(Wc + c1 * 2 + 1);
        }
        float bc0 = __ldg(bc), bc1 = __ldg(bc + 1);
#pragma unroll
        for (int i2 = 0; i2 < 4; i2++) {
            int m0 = row0 + ty * 8 + i2 * 2;
            int m1 = m0 + 1;
            float p0lo = 0.f, p1lo = 0.f, p0hi = 0.f, p1hi = 0.f;
#pragma unroll
            for (int j = 0; j < 4; j++) {
                float2 v = unpack2(acc[i2][j]);
                float lo = v.x + bA[j], hi = v.y + bA[j];
                p0lo += lo * wc0[j]; p1lo += lo * wc1[j];
                p0hi += hi * wc0[j]; p1hi += hi * wc1[j];
                float2 w = unpack2(acc[i2][j + 4]);
                float lo2 = w.x + bB[j], hi2 = w.y + bB[j];
                p0lo += lo2 * wc0[j + 4]; p1lo += lo2 * wc1[j + 4];
                p0hi += hi2 * wc0[j + 4]; p1hi += hi2 * wc1[j + 4];
            }
#pragma unroll
            for (int off = 8; off; off >>= 1) {
                p0lo += __shfl_xor_sync(0xFFFFFFFFu, p0lo, off);
                p1lo += __shfl_xor_sync(0xFFFFFFFFu, p1lo, off);
                p0hi += __shfl_xor_sync(0xFFFFFFFFu, p0hi, off);
                p1hi += __shfl_xor_sync(0xFFFFFFFFu, p1hi, off);
            }
            if (tx == 0) {
                if (m0 < M) {
                    out2[(size_t)m0 * 2 + 0] = p0lo + bc0;
                    out2[(size_t)m0 * 2 + 1] = p1lo + bc1;
                }
                if (m1 < M) {
                    out2[(size_t)m1 * 2 + 0] = p0hi + bc0;
                    out2[(size_t)m1 * 2 + 1] = p1hi + bc1;
                }
            }
        }
    }
}

// ---------------------------------------------------------------- launch
extern "C" void kernel_launch(void* const* d_in, const int* in_sizes, int n_in,
                              void* d_out, int out_size) {
    const float* features = (const float*)d_in[0];
    const int*   src      = (const int*)d_in[1];
    const int*   dst      = (const int*)d_in[2];
    const float* W1s      = (const float*)d_in[3];
    const float* W1n      = (const float*)d_in[4];
    const float* b1       = (const float*)d_in[5];
    const float* W2s      = (const float*)d_in[6];
    const float* W2n      = (const float*)d_in[7];
    const float* b2       = (const float*)d_in[8];
    const float* Wc       = (const float*)d_in[9];
    const float* bc       = (const float*)d_in[10];

    int N = in_sizes[0] / D;
    int E = in_sizes[1];

    int *cnt, *cursor, *rowstart, *csrsrc;
    float *agg, *h1;
    cudaGetSymbolAddress((void**)&cnt, g_cnt);
    cudaGetSymbolAddress((void**)&cursor, g_cursor);
    cudaGetSymbolAddress((void**)&rowstart, g_rowstart);
    cudaGetSymbolAddress((void**)&csrsrc, g_csrsrc);
    cudaGetSymbolAddress((void**)&agg, g_agg);
    cudaGetSymbolAddress((void**)&h1, g_h1);

    int mblocks = (N + 127) / 128;
    int gblocks = (N + 7) / 8;  // warp per node, 8 warps/block

    // CSR build
    cudaMemsetAsync(cnt, 0, (size_t)N * sizeof(int));
    hist_kernel<<<(E + 255) / 256, 256>>>(dst, cnt, E);
    scan_kernel<<<1, 1024>>>(cnt, rowstart, cursor, N);
    fill_kernel<<<(E + 255) / 256, 256>>>(src, dst, cursor, csrsrc, E);

    // layer 1
    gather_kernel<<<gblocks, 256>>>(features, rowstart, csrsrc, agg, N);
    gemm_sage<<<mblocks, 256>>>(features, agg, W1s, W1n, b1, h1, N, 0,
                                nullptr, nullptr, nullptr);

    // layer 2 (+ fused classifier)
    gather_kernel<<<gblocks, 256>>>(h1, rowstart, csrsrc, agg, N);
    gemm_sage<<<mblocks, 256>>>(h1, agg, W2s, W2n, b2, nullptr, N, 1,
                                Wc, bc, (float*)d_out);
}